// round 8
// baseline (speedup 1.0000x reference)
#include <cuda_runtime.h>

// CosmosUnpatcher3d: one Haar IDWT level (2,24,9,256,256) -> slice -> (2,3,17,512,512).
// Each 2x2x2 output block is the 8-point WHT of the 8 band values (tap product = 1).
//
// R8: persistent software-pipelined kernel. 768 blocks x 9 iterations = 6912
// tiles (exact). Per iteration: WHT from current loads, then ISSUE NEXT TILE'S
// 8 LOADS BEFORE THE 4 STORES -> read stream stays saturated through the
// store-drain phase (R1's warps are store-only at end of life; that is the
// last untested R/W-interleaving slack).
//
// Iteration stride 768*256 = 6*2^15: wp/h are loop-invariant; plane index
// r advances by 6. Input plane = r + 189*(r/27); output plane from bc=r/9.

#define BAND_STRIDE2 (3 * 9 * 256 * 128)   // band stride in float2 units
#define NBLK 768
#define NIT  9

__device__ __forceinline__ void wht8(const float v0, const float v1, const float v2,
                                     const float v3, const float v4, const float v5,
                                     const float v6, const float v7, float o[8]) {
    float a0 = v0 + v1, a1 = v0 - v1;
    float a2 = v2 + v3, a3 = v2 - v3;
    float a4 = v4 + v5, a5 = v4 - v5;
    float a6 = v6 + v7, a7 = v6 - v7;
    float b0 = a0 + a2, b2 = a0 - a2;
    float b1 = a1 + a3, b3 = a1 - a3;
    float b4 = a4 + a6, b6 = a4 - a6;
    float b5 = a5 + a7, b7 = a5 - a7;
    o[0] = b0 + b4; o[4] = b0 - b4;
    o[1] = b1 + b5; o[5] = b1 - b5;
    o[2] = b2 + b6; o[6] = b2 - b6;
    o[3] = b3 + b7; o[7] = b3 - b7;
}

__device__ __forceinline__ int input_base(int r, int h, int wp) {
    int b = r / 27;                       // batch
    int plane = r + 189 * b;              // (b*24+ch)*9 + t
    return plane * 32768 + (h << 7) + wp; // float2 units
}

__global__ __launch_bounds__(256)
void idwt_haar_kernel(const float2* __restrict__ in, float* __restrict__ out) {
    int tid0 = blockIdx.x * 256 + threadIdx.x;
    int wp = tid0 & 127;          // loop-invariant
    int h  = (tid0 >> 7) & 255;   // loop-invariant
    int r0 = tid0 >> 15;          // [0,6); advances by 6 per iteration

    // prologue: load tile 0
    float2 v[8];
    {
        int ib = input_base(r0, h, wp);
#pragma unroll
        for (int s = 0; s < 8; s++) v[s] = in[ib + s * BAND_STRIDE2];
    }

    int r = r0;
#pragma unroll
    for (int it = 0; it < NIT; it++) {
        // compute current tile (v dies here)
        float x[8], y[8];
        wht8(v[0].x, v[1].x, v[2].x, v[3].x, v[4].x, v[5].x, v[6].x, v[7].x, x);
        wht8(v[0].y, v[1].y, v[2].y, v[3].y, v[4].y, v[5].y, v[6].y, v[7].y, y);

        int bc = r / 9;            // b*3 + ch
        int t  = r - bc * 9;

        // prefetch next tile BEFORE stores
        if (it < NIT - 1) {
            int rn = r + 6;
            int ib = input_base(rn, h, wp);
#pragma unroll
            for (int s = 0; s < 8; s++) v[s] = in[ib + s * BAND_STRIDE2];
        }

        // stores for current tile: out (2,3,17,512,512), t2 = 2t + pt - 1
#pragma unroll
        for (int pt = 0; pt < 2; pt++) {
            int t2 = 2 * t + pt - 1;
            if (t2 < 0) continue;
#pragma unroll
            for (int ph = 0; ph < 2; ph++) {
                int p = pt * 4 + ph * 2;
                int obase = ((bc * 17 + t2) << 18) + (((h << 1) + ph) << 9) + (wp << 2);
                *(float4*)(out + obase) = make_float4(x[p], x[p + 1], y[p], y[p + 1]);
            }
        }
        r += 6;
    }
}

extern "C" void kernel_launch(void* const* d_in, const int* in_sizes, int n_in,
                              void* d_out, int out_size) {
    const float2* in = (const float2*)d_in[0];
    float* out = (float*)d_out;
    idwt_haar_kernel<<<NBLK, 256>>>(in, out);
}

// round 9
// speedup vs baseline: 1.0544x; 1.0544x over previous
#include <cuda_runtime.h>

// CosmosUnpatcher3d — FINAL.
// One Haar IDWT level (2,24,9,256,256) -> T-slice -> (2,3,17,512,512).
// Combined tap c^3*sqrt(8) = 1 exactly, so each 2x2x2 output block is the
// 8-point Walsh-Hadamard transform of the 8 band values at that (t,h,w):
//   out[2t+pt-1, 2h+ph, 2w+pw] = sum_band (-1)^popcount(band & parity) * in[band]
//
// Design (confirmed optimal over a 7-variant matrix, R1-R8):
//  - one thread per input float2 per (b,ch,t,h): 8 coalesced band loads,
//    MLP=8, 64B in flight per thread at 32 regs -> ~80% occupancy
//  - two register WHT-8 butterflies (24 FADD per 16 outputs)
//  - up to 4 coalesced float4 stores (512B/warp full-line runs)
//  - default cache policy (cs/cg/wt neutral or worse), exact grid, no smem.
// Measured: 5.9TB/s sustained = mixed read/write HBM ceiling for this
// pattern on GB300; pipelining/chunking/wide-load variants all regressed
// via register pressure -> occupancy -> bytes-in-flight.

#define BAND_STRIDE2 (3 * 9 * 256 * 128)   // band stride in float2 units

__device__ __forceinline__ void wht8(const float v0, const float v1, const float v2,
                                     const float v3, const float v4, const float v5,
                                     const float v6, const float v7, float o[8]) {
    float a0 = v0 + v1, a1 = v0 - v1;
    float a2 = v2 + v3, a3 = v2 - v3;
    float a4 = v4 + v5, a5 = v4 - v5;
    float a6 = v6 + v7, a7 = v6 - v7;
    float b0 = a0 + a2, b2 = a0 - a2;
    float b1 = a1 + a3, b3 = a1 - a3;
    float b4 = a4 + a6, b6 = a4 - a6;
    float b5 = a5 + a7, b7 = a5 - a7;
    o[0] = b0 + b4; o[4] = b0 - b4;
    o[1] = b1 + b5; o[5] = b1 - b5;
    o[2] = b2 + b6; o[6] = b2 - b6;
    o[3] = b3 + b7; o[7] = b3 - b7;
}

__global__ __launch_bounds__(256)
void idwt_haar_kernel(const float* __restrict__ in, float* __restrict__ out) {
    int tid = blockIdx.x * 256 + threadIdx.x;
    // total threads = 2*3*9*256*128 = 1,769,472 (exact grid, no tail check)
    int wp = tid & 127;          // w-pair index [0,128)
    int h  = (tid >> 7) & 255;   // input h [0,256)
    int r  = tid >> 15;          // [0,54) = (b*3+ch)*9 + t
    int t  = r % 9;
    int bc = r / 9;              // b*3 + ch
    int b  = bc / 3;
    int ch = bc - 3 * b;

    // input base in float2 units
    int ibase2 = ((((b * 24 + ch) * 9 + t) << 16) + (h << 8) + (wp << 1)) >> 1;
    const float2* in2 = (const float2*)in;

    float2 v0 = in2[ibase2 + 0 * BAND_STRIDE2];
    float2 v1 = in2[ibase2 + 1 * BAND_STRIDE2];
    float2 v2 = in2[ibase2 + 2 * BAND_STRIDE2];
    float2 v3 = in2[ibase2 + 3 * BAND_STRIDE2];
    float2 v4 = in2[ibase2 + 4 * BAND_STRIDE2];
    float2 v5 = in2[ibase2 + 5 * BAND_STRIDE2];
    float2 v6 = in2[ibase2 + 6 * BAND_STRIDE2];
    float2 v7 = in2[ibase2 + 7 * BAND_STRIDE2];

    float x[8], y[8];
    wht8(v0.x, v1.x, v2.x, v3.x, v4.x, v5.x, v6.x, v7.x, x);
    wht8(v0.y, v1.y, v2.y, v3.y, v4.y, v5.y, v6.y, v7.y, y);

    // Output (2,3,17,512,512): t2 = 2t + pt - 1 (drop t2 < 0).
#pragma unroll
    for (int pt = 0; pt < 2; pt++) {
        int t2 = 2 * t + pt - 1;
        if (t2 < 0) continue;
#pragma unroll
        for (int ph = 0; ph < 2; ph++) {
            int p = pt * 4 + ph * 2;
            int obase = ((bc * 17 + t2) << 18) + (((h << 1) + ph) << 9) + (wp << 2);
            *(float4*)(out + obase) = make_float4(x[p], x[p + 1], y[p], y[p + 1]);
        }
    }
}

extern "C" void kernel_launch(void* const* d_in, const int* in_sizes, int n_in,
                              void* d_out, int out_size) {
    const float* in = (const float*)d_in[0];
    float* out = (float*)d_out;
    // 1,769,472 threads / 256 = 6912 blocks
    idwt_haar_kernel<<<6912, 256>>>(in, out);
}

// round 10
// speedup vs baseline: 1.0553x; 1.0009x over previous
#include <cuda_runtime.h>

// CosmosUnpatcher3d — FINAL (3x confirmed: 37.38 / 37.60 / 37.63 us).
// One Haar IDWT level (2,24,9,256,256) -> T-slice -> (2,3,17,512,512).
// Combined tap c^3*sqrt(8) = 1 exactly, so each 2x2x2 output block is the
// 8-point Walsh-Hadamard transform of the 8 band values at that (t,h,w):
//   out[2t+pt-1, 2h+ph, 2w+pw] = sum_band (-1)^popcount(band & parity) * in[band]
//
// Design (optimal over an 8-axis matrix, R1-R9):
//  - one thread per input float2 per (b,ch,t,h): 8 coalesced band loads,
//    MLP=8, 32 regs -> ~80% achieved occupancy (full RF: 32x2048 = 64K regs)
//  - two register WHT-8 butterflies (24 FADD per 16 outputs)
//  - up to 4 coalesced float4 stores (512B/warp full-line runs)
//  - default cache policy; exact grid; no smem.
// Measured ceiling: 5.9TB/s sustained = mixed read/write HBM limit for this
// pattern (220MB irreducible traffic, zero reuse). Falsified alternatives:
// .cs/.cg/.wt policies (neutral/worse), float4 loads (regs 57 -> occ 38%),
// h-chunking (regs 41 -> occ 53%), 128-thr blocks (neutral), persistent
// prefetch pipeline (regs 54 -> occ 43%). DRAM%% tracked occupancy only.

#define BAND_STRIDE2 (3 * 9 * 256 * 128)   // band stride in float2 units

__device__ __forceinline__ void wht8(const float v0, const float v1, const float v2,
                                     const float v3, const float v4, const float v5,
                                     const float v6, const float v7, float o[8]) {
    float a0 = v0 + v1, a1 = v0 - v1;
    float a2 = v2 + v3, a3 = v2 - v3;
    float a4 = v4 + v5, a5 = v4 - v5;
    float a6 = v6 + v7, a7 = v6 - v7;
    float b0 = a0 + a2, b2 = a0 - a2;
    float b1 = a1 + a3, b3 = a1 - a3;
    float b4 = a4 + a6, b6 = a4 - a6;
    float b5 = a5 + a7, b7 = a5 - a7;
    o[0] = b0 + b4; o[4] = b0 - b4;
    o[1] = b1 + b5; o[5] = b1 - b5;
    o[2] = b2 + b6; o[6] = b2 - b6;
    o[3] = b3 + b7; o[7] = b3 - b7;
}

__global__ __launch_bounds__(256)
void idwt_haar_kernel(const float* __restrict__ in, float* __restrict__ out) {
    int tid = blockIdx.x * 256 + threadIdx.x;
    // total threads = 2*3*9*256*128 = 1,769,472 (exact grid, no tail check)
    int wp = tid & 127;          // w-pair index [0,128)
    int h  = (tid >> 7) & 255;   // input h [0,256)
    int r  = tid >> 15;          // [0,54) = (b*3+ch)*9 + t
    int t  = r % 9;
    int bc = r / 9;              // b*3 + ch
    int b  = bc / 3;
    int ch = bc - 3 * b;

    // input base in float2 units
    int ibase2 = ((((b * 24 + ch) * 9 + t) << 16) + (h << 8) + (wp << 1)) >> 1;
    const float2* in2 = (const float2*)in;

    float2 v0 = in2[ibase2 + 0 * BAND_STRIDE2];
    float2 v1 = in2[ibase2 + 1 * BAND_STRIDE2];
    float2 v2 = in2[ibase2 + 2 * BAND_STRIDE2];
    float2 v3 = in2[ibase2 + 3 * BAND_STRIDE2];
    float2 v4 = in2[ibase2 + 4 * BAND_STRIDE2];
    float2 v5 = in2[ibase2 + 5 * BAND_STRIDE2];
    float2 v6 = in2[ibase2 + 6 * BAND_STRIDE2];
    float2 v7 = in2[ibase2 + 7 * BAND_STRIDE2];

    float x[8], y[8];
    wht8(v0.x, v1.x, v2.x, v3.x, v4.x, v5.x, v6.x, v7.x, x);
    wht8(v0.y, v1.y, v2.y, v3.y, v4.y, v5.y, v6.y, v7.y, y);

    // Output (2,3,17,512,512): t2 = 2t + pt - 1 (drop t2 < 0).
#pragma unroll
    for (int pt = 0; pt < 2; pt++) {
        int t2 = 2 * t + pt - 1;
        if (t2 < 0) continue;
#pragma unroll
        for (int ph = 0; ph < 2; ph++) {
            int p = pt * 4 + ph * 2;
            int obase = ((bc * 17 + t2) << 18) + (((h << 1) + ph) << 9) + (wp << 2);
            *(float4*)(out + obase) = make_float4(x[p], x[p + 1], y[p], y[p + 1]);
        }
    }
}

extern "C" void kernel_launch(void* const* d_in, const int* in_sizes, int n_in,
                              void* d_out, int out_size) {
    const float* in = (const float*)d_in[0];
    float* out = (float*)d_out;
    // 1,769,472 threads / 256 = 6912 blocks
    idwt_haar_kernel<<<6912, 256>>>(in, out);
}

// round 11
// speedup vs baseline: 1.0616x; 1.0060x over previous
#include <cuda_runtime.h>

// CosmosUnpatcher3d: one Haar IDWT level (2,24,9,256,256) -> T-slice -> (2,3,17,512,512).
// Combined tap c^3*sqrt(8) = 1 exactly: each 2x2x2 output block is the 8-point
// Walsh-Hadamard transform of the 8 band values at that (t,h,w).
//
// R11 = confirmed-optimal R1 body (32 regs, ~79% occ, float2 loads, float4
// stores, exact grid) with ONE change: write-through stores (__stwt).
// Rationale: harness runs back-to-back graph replays; default stores leave
// ~dirty output lines in L2 whose writeback drains into the NEXT replay's
// read phase. Write-through streams stores to DRAM within this replay's
// write windows and ends the kernel with a clean L2. Last untested store
// policy (default / .cs already measured; .wt distinct from both).

#define BAND_STRIDE2 (3 * 9 * 256 * 128)   // band stride in float2 units

__device__ __forceinline__ void wht8(const float v0, const float v1, const float v2,
                                     const float v3, const float v4, const float v5,
                                     const float v6, const float v7, float o[8]) {
    float a0 = v0 + v1, a1 = v0 - v1;
    float a2 = v2 + v3, a3 = v2 - v3;
    float a4 = v4 + v5, a5 = v4 - v5;
    float a6 = v6 + v7, a7 = v6 - v7;
    float b0 = a0 + a2, b2 = a0 - a2;
    float b1 = a1 + a3, b3 = a1 - a3;
    float b4 = a4 + a6, b6 = a4 - a6;
    float b5 = a5 + a7, b7 = a5 - a7;
    o[0] = b0 + b4; o[4] = b0 - b4;
    o[1] = b1 + b5; o[5] = b1 - b5;
    o[2] = b2 + b6; o[6] = b2 - b6;
    o[3] = b3 + b7; o[7] = b3 - b7;
}

__global__ __launch_bounds__(256)
void idwt_haar_kernel(const float* __restrict__ in, float* __restrict__ out) {
    int tid = blockIdx.x * 256 + threadIdx.x;
    // total threads = 2*3*9*256*128 = 1,769,472 (exact grid, no tail check)
    int wp = tid & 127;          // w-pair index [0,128)
    int h  = (tid >> 7) & 255;   // input h [0,256)
    int r  = tid >> 15;          // [0,54) = (b*3+ch)*9 + t
    int t  = r % 9;
    int bc = r / 9;              // b*3 + ch
    int b  = bc / 3;
    int ch = bc - 3 * b;

    // input base in float2 units
    int ibase2 = ((((b * 24 + ch) * 9 + t) << 16) + (h << 8) + (wp << 1)) >> 1;
    const float2* in2 = (const float2*)in;

    float2 v0 = in2[ibase2 + 0 * BAND_STRIDE2];
    float2 v1 = in2[ibase2 + 1 * BAND_STRIDE2];
    float2 v2 = in2[ibase2 + 2 * BAND_STRIDE2];
    float2 v3 = in2[ibase2 + 3 * BAND_STRIDE2];
    float2 v4 = in2[ibase2 + 4 * BAND_STRIDE2];
    float2 v5 = in2[ibase2 + 5 * BAND_STRIDE2];
    float2 v6 = in2[ibase2 + 6 * BAND_STRIDE2];
    float2 v7 = in2[ibase2 + 7 * BAND_STRIDE2];

    float x[8], y[8];
    wht8(v0.x, v1.x, v2.x, v3.x, v4.x, v5.x, v6.x, v7.x, x);
    wht8(v0.y, v1.y, v2.y, v3.y, v4.y, v5.y, v6.y, v7.y, y);

    // Output (2,3,17,512,512): t2 = 2t + pt - 1 (drop t2 < 0).
#pragma unroll
    for (int pt = 0; pt < 2; pt++) {
        int t2 = 2 * t + pt - 1;
        if (t2 < 0) continue;
#pragma unroll
        for (int ph = 0; ph < 2; ph++) {
            int p = pt * 4 + ph * 2;
            int obase = ((bc * 17 + t2) << 18) + (((h << 1) + ph) << 9) + (wp << 2);
            __stwt((float4*)(out + obase),
                   make_float4(x[p], x[p + 1], y[p], y[p + 1]));
        }
    }
}

extern "C" void kernel_launch(void* const* d_in, const int* in_sizes, int n_in,
                              void* d_out, int out_size) {
    const float* in = (const float*)d_in[0];
    float* out = (float*)d_out;
    // 1,769,472 threads / 256 = 6912 blocks
    idwt_haar_kernel<<<6912, 256>>>(in, out);
}